// round 1
// baseline (speedup 1.0000x reference)
#include <cuda_runtime.h>
#include <math.h>

// SwapV2: Gaussian-weighted spatial warp (soft gather), truncated at 5 sigma.
// B=8, C=32, H=W=64, fp32.
//
// Grid: (32 pixel-tiles, 8 batches). Block: 256 threads = 8 warps, 128 pixels.
// Each warp owns 16 output pixels. Lane = source column offset within the
// (<=31 wide) truncated x-window. Input channels staged 4-at-a-time in smem.

#define BB 8
#define CCN 32
#define HH 64
#define WW 64
#define HWP 4096      // H*W
#define PIXB 128      // pixels per block
#define NW 8          // warps per block
#define QPW 16        // pixels per warp
#define CCH 4         // channels per smem chunk
#define NCHUNK (CCN / CCH)
#define KTRUNC 5.0f

#define SMEM_BYTES (CCH * HWP * 4 + NW * QPW * 32 * 4)  // 64KB + 16KB

__global__ __launch_bounds__(256, 2)
void swapv2_kernel(const float* __restrict__ inp,
                   const float* __restrict__ exPx,
                   const float* __restrict__ exPy,
                   const float* __restrict__ sigx,
                   const float* __restrict__ sigy,
                   float* __restrict__ out)
{
    extern __shared__ float smem[];
    float* s_in = smem;                 // [CCH][HWP]
    float* s_wy = smem + CCH * HWP;     // [NW][QPW][32]

    const int tid  = threadIdx.x;
    const int w    = tid >> 5;
    const int lane = tid & 31;
    const int tile = blockIdx.x;        // 0..31
    const int b    = blockIdx.y;        // 0..7
    const int pbase = tile * PIXB;

    // ---- per-pixel setup: windows, weights, normalization ----
    float wxr[QPW];     // this lane's wx for pixel q
    float invZ[QPW];    // 1/Z (uniform across warp)
    int   meta[QPW];    // packed u0 | wu<<8 | v0<<16

    #pragma unroll
    for (int q = 0; q < QPW; q++) {
        int pg  = pbase + w * QPW + q;      // pixel index within batch (i*64+j)
        int idx = b * HWP + pg;
        float ey = exPy[idx], ex = exPx[idx];
        float sy = sigy[idx], sx = sigx[idx];

        int u0 = max(0,      (int)ceilf (ey - KTRUNC * sy));
        int u1 = min(HH - 1, (int)floorf(ey + KTRUNC * sy));
        int v0 = max(0,      (int)ceilf (ex - KTRUNC * sx));
        int v1 = min(WW - 1, (int)floorf(ex + KTRUNC * sx));

        float invsy = 1.0f / sy, invsx = 1.0f / sx;

        int uu = u0 + lane;
        float dy = ((float)uu - ey) * invsy;
        float wy = (uu <= u1) ? expf(-0.5f * dy * dy) : 0.0f;
        s_wy[(w * QPW + q) * 32 + lane] = wy;

        int vv = v0 + lane;
        float dx = ((float)vv - ex) * invsx;
        float wx = (vv <= v1) ? expf(-0.5f * dx * dx) : 0.0f;
        wxr[q] = wx;

        float sumy = wy, sumx = wx;
        #pragma unroll
        for (int o = 16; o; o >>= 1) {
            sumy += __shfl_xor_sync(0xFFFFFFFFu, sumy, o);
            sumx += __shfl_xor_sync(0xFFFFFFFFu, sumx, o);
        }
        invZ[q] = 1.0f / (sumy * sumx + 1e-8f);
        meta[q] = u0 | ((u1 - u0 + 1) << 8) | (v0 << 16);
    }
    __syncwarp();

    // ---- main loop over channel chunks ----
    for (int ch = 0; ch < NCHUNK; ch++) {
        __syncthreads();
        // stage CCH channels into smem (coalesced float4)
        {
            const float4* g4 = (const float4*)(inp + ((b * CCN + ch * CCH) * HWP));
            float4* s4 = (float4*)s_in;
            #pragma unroll
            for (int k = 0; k < (CCH * HWP / 4) / 256; k++)
                s4[tid + k * 256] = g4[tid + k * 256];
        }
        __syncthreads();

        #pragma unroll
        for (int q = 0; q < QPW; q++) {
            int m  = meta[q];
            int u0 = m & 0xFF;
            int wu = (m >> 8) & 0xFF;
            int v0 = (m >> 16) & 0xFF;

            int vv   = v0 + lane;
            int vidx = min(vv, WW - 1);           // clamped; wx=0 masks it
            const float* p0  = s_in + u0 * WW + vidx;
            const float* pwy = s_wy + (w * QPW + q) * 32;

            float a0 = 0.f, a1 = 0.f, a2 = 0.f, a3 = 0.f;
            #pragma unroll 4
            for (int t = 0; t < wu; t++) {
                float wy = pwy[t];                 // broadcast LDS
                const float* p = p0 + t * WW;
                a0 += wy * p[0 * HWP];
                a1 += wy * p[1 * HWP];
                a2 += wy * p[2 * HWP];
                a3 += wy * p[3 * HWP];
            }
            float wx = wxr[q];
            a0 *= wx; a1 *= wx; a2 *= wx; a3 *= wx;
            #pragma unroll
            for (int o = 16; o; o >>= 1) {
                a0 += __shfl_xor_sync(0xFFFFFFFFu, a0, o);
                a1 += __shfl_xor_sync(0xFFFFFFFFu, a1, o);
                a2 += __shfl_xor_sync(0xFFFFFFFFu, a2, o);
                a3 += __shfl_xor_sync(0xFFFFFFFFu, a3, o);
            }
            if (lane < CCH) {
                float r = (lane == 0) ? a0 : (lane == 1) ? a1 : (lane == 2) ? a2 : a3;
                int pg = pbase + w * QPW + q;
                out[(b * CCN + ch * CCH + lane) * HWP + pg] = r * invZ[q];
            }
        }
    }
}

extern "C" void kernel_launch(void* const* d_in, const int* in_sizes, int n_in,
                              void* d_out, int out_size) {
    (void)in_sizes; (void)n_in; (void)out_size;
    const float* inp  = (const float*)d_in[0];
    const float* exPx = (const float*)d_in[1];
    const float* exPy = (const float*)d_in[2];
    const float* sigx = (const float*)d_in[3];
    const float* sigy = (const float*)d_in[4];
    float* out = (float*)d_out;

    cudaFuncSetAttribute(swapv2_kernel,
                         cudaFuncAttributeMaxDynamicSharedMemorySize, SMEM_BYTES);
    dim3 grid(HWP / PIXB, BB);   // (32, 8)
    swapv2_kernel<<<grid, 256, SMEM_BYTES>>>(inp, exPx, exPy, sigx, sigy, out);
}

// round 2
// speedup vs baseline: 1.2748x; 1.2748x over previous
#include <cuda_runtime.h>
#include <cuda_fp16.h>
#include <math.h>

// SwapV2: Gaussian soft-gather, truncated at 5 sigma. B=8, C=32, H=W=64 fp32.
//
// R2 design: channel-in-lane (lane = channel, no idle lanes, no reductions),
// fp16 image staged in smem as two overlapping 48-row u-slabs per batch.
// Window height <= 31, so u0<=17 -> slab 0 ([0,48)), else slab 1 ([16,64)).
// smem layout: s_in[u][c][70 halves] (stride 70 halves = 35 words -> bank 3c,
// conflict-free), v-pads 64..69 zeroed so over-read * wx==0 stays 0.

#define HH 64
#define WW 64
#define HWP 4096
#define CCN 32
#define SLAB_ROWS 48
#define ROWH 70                       // halves per (u,c) row incl 6-half pad
#define NWARPS 32                     // 1024 threads
#define PTILES 9                      // grid.x -> 9*2*8 = 144 blocks (1 wave)
#define KTRUNC 5.0f

#define SIN_HALVES (SLAB_ROWS * CCN * ROWH)        // 107520 halves
#define SIN_BYTES  (SIN_HALVES * 2)                // 215040
#define SW_BYTES   (NWARPS * 64 * 4)               // wx[32]+wy[32] per warp: 8192
#define SMEM_BYTES (SIN_BYTES + SW_BYTES)          // 223232 <= 232448

__global__ __launch_bounds__(1024, 1)
void swapv2_kernel(const float* __restrict__ inp,
                   const float* __restrict__ exPx,
                   const float* __restrict__ exPy,
                   const float* __restrict__ sigx,
                   const float* __restrict__ sigy,
                   float* __restrict__ out)
{
    extern __shared__ char smem[];
    __half* s_in = (__half*)smem;
    float*  s_w  = (float*)(smem + SIN_BYTES);     // [warp][64]: 0..31 wx, 32..63 wy

    const int tid  = threadIdx.x;
    const int w    = tid >> 5;
    const int lane = tid & 31;
    const int tile = blockIdx.x;      // 0..8
    const int slab = blockIdx.y;      // 0..1
    const int b    = blockIdx.z;      // 0..7
    const int ubase = slab * 16;      // slab 0: rows [0,48); slab 1: [16,64)

    // ---- stage 48-row fp16 slab: layout [u][c][ROWH], pads zeroed ----
    {
        const float* gsrc = inp + b * CCN * HWP;
        for (int j = tid; j < SLAB_ROWS * CCN * 35; j += 1024) {
            int vp = j % 35;                  // half2 pair index (32..34 = pad)
            int r  = j / 35;                  // row = u*32 + c
            int u  = r >> 5;
            int c  = r & 31;
            __half2 h = __float2half2_rn(0.0f);
            if (vp < 32) {
                float2 g = *(const float2*)(gsrc + c * HWP + (ubase + u) * WW + 2 * vp);
                h = __float22half2_rn(g);
            }
            *(__half2*)(s_in + r * ROWH + 2 * vp) = h;
        }
    }
    __syncthreads();

    // ---- pixel loop: one warp per output pixel ----
    const int pbeg = (HWP * tile) / PTILES;
    const int pend = (HWP * (tile + 1)) / PTILES;
    float* s_wx = s_w + w * 64;
    float* s_wy = s_wx + 32;

    for (int p = pbeg + w; p < pend; p += NWARPS) {
        const int idx = b * HWP + p;
        float ey = exPy[idx], sy = sigy[idx];

        int u0 = max(0,      (int)ceilf (ey - KTRUNC * sy));
        int myslab = (u0 <= 17) ? 0 : 1;
        if (myslab != slab) continue;
        int u1 = min(HH - 1, (int)floorf(ey + KTRUNC * sy));

        float ex = exPx[idx], sx = sigx[idx];
        int v0 = max(0,      (int)ceilf (ex - KTRUNC * sx));
        int v1 = min(WW - 1, (int)floorf(ex + KTRUNC * sx));
        int vh0 = v0 & ~1;

        // per-lane weights
        float invsy = 1.0f / sy, invsx = 1.0f / sx;
        int vv = vh0 + lane;
        float dx = ((float)vv - ex) * invsx;
        float wx = (vv >= v0 && vv <= v1) ? __expf(-0.5f * dx * dx) : 0.0f;
        int uu = u0 + lane;
        float dy = ((float)uu - ey) * invsy;
        float wy = (uu <= u1) ? __expf(-0.5f * dy * dy) : 0.0f;
        // exact exp for the mass terms too (fast exp rel err ~1e-6, fine)
        float sumx = wx, sumy = wy;
        #pragma unroll
        for (int o = 16; o; o >>= 1) {
            sumx += __shfl_xor_sync(0xFFFFFFFFu, sumx, o);
            sumy += __shfl_xor_sync(0xFFFFFFFFu, sumy, o);
        }
        float invZ = 1.0f / (sumx * sumy + 1e-8f);
        s_wx[lane] = wx;
        s_wy[lane] = wy;
        __syncwarp();

        const int wu  = u1 - u0 + 1;                 // <= 31
        const int nv4 = ((v1 - vh0) >> 2) + 1;       // 2-pair iters, <= 8

        // lane = channel c
        const __half* row = s_in + ((u0 - ubase) * CCN + lane) * ROWH + vh0;
        float acc = 0.0f;

        for (int t = 0; t < wu; t++) {
            float wyt = s_wy[t];                     // broadcast LDS
            const __half* hp = row + t * (CCN * ROWH);
            float s0 = 0.0f, s1 = 0.0f;
            #pragma unroll 4
            for (int k = 0; k < nv4; k++) {
                float4 wx4 = *(const float4*)(s_wx + 4 * k);   // broadcast LDS.128
                __half2 ha = *(const __half2*)(hp + 4 * k);
                __half2 hb = *(const __half2*)(hp + 4 * k + 2);
                float2 fa = __half22float2(ha);
                float2 fb = __half22float2(hb);
                s0 = fmaf(wx4.x, fa.x, s0);
                s1 = fmaf(wx4.y, fa.y, s1);
                s0 = fmaf(wx4.z, fb.x, s0);
                s1 = fmaf(wx4.w, fb.y, s1);
            }
            acc = fmaf(wyt, s0 + s1, acc);
        }

        out[(b * CCN + lane) * HWP + p] = acc * invZ;
        __syncwarp();
    }
}

extern "C" void kernel_launch(void* const* d_in, const int* in_sizes, int n_in,
                              void* d_out, int out_size) {
    (void)in_sizes; (void)n_in; (void)out_size;
    const float* inp  = (const float*)d_in[0];
    const float* exPx = (const float*)d_in[1];
    const float* exPy = (const float*)d_in[2];
    const float* sigx = (const float*)d_in[3];
    const float* sigy = (const float*)d_in[4];
    float* out = (float*)d_out;

    cudaFuncSetAttribute(swapv2_kernel,
                         cudaFuncAttributeMaxDynamicSharedMemorySize, SMEM_BYTES);
    dim3 grid(PTILES, 2, 8);          // 144 blocks = one full wave
    swapv2_kernel<<<grid, 1024, SMEM_BYTES>>>(inp, exPx, exPy, sigx, sigy, out);
}

// round 3
// speedup vs baseline: 1.7124x; 1.3432x over previous
#include <cuda_runtime.h>
#include <math.h>

// SwapV2: Gaussian soft-gather, 5-sigma truncated. B=8, C=32, H=W=64 fp32.
//
// R3: fp32 smem + packed fma.rn.f32x2 (FFMA2), channel-split (16 ch/block),
// lane = (vhalf, channel), wx hoisted to registers, wy broadcast from smem.
// Two overlapping 48-row u-slabs; window height <= 31 guarantees fit.

#define HH 64
#define WW 64
#define HWP 4096
#define CG 16                 // channels per block
#define SLAB_ROWS 48
#define ROWF 68               // floats per (u,c) row incl 4-float pad
#define NWARPS 32
#define PTILES 9
#define KTRUNC 5.0f

#define SIN_FLOATS (SLAB_ROWS * CG * ROWF)   // 52224
#define SW_FLOATS  (NWARPS * 72)             // per warp: wy[32] + wx[40]
#define SMEM_BYTES ((SIN_FLOATS + SW_FLOATS) * 4)   // 218112

typedef unsigned long long ull;

#define FMA2(d, a, b, c) asm("fma.rn.f32x2 %0, %1, %2, %3;" : "=l"(d) : "l"(a), "l"(b), "l"(c))
#define PACK2(d, lo, hi) asm("mov.b64 %0, {%1, %2};" : "=l"(d) : "f"(lo), "f"(hi))
#define UNPACK2(lo, hi, s) asm("mov.b64 {%0, %1}, %2;" : "=f"(lo), "=f"(hi) : "l"(s))

__global__ __launch_bounds__(1024, 1)
void swapv2_kernel(const float* __restrict__ inp,
                   const float* __restrict__ exPx,
                   const float* __restrict__ exPy,
                   const float* __restrict__ sigx,
                   const float* __restrict__ sigy,
                   float* __restrict__ out)
{
    extern __shared__ float smem[];
    float* s_in = smem;                     // [u(48)][c(16)][ROWF]
    float* s_w  = smem + SIN_FLOATS;

    const int tid  = threadIdx.x;
    const int w    = tid >> 5;
    const int lane = tid & 31;
    const int cl   = lane & 15;             // channel within group
    const int hf   = lane >> 4;             // v-chunk half (0/1)
    const int tile = blockIdx.x;            // 0..8
    const int slab = blockIdx.y & 1;        // 0..1
    const int cg   = blockIdx.y >> 1;       // 0..1 channel group
    const int b    = blockIdx.z;            // 0..7
    const int ubase = slab * 16;            // slab0: [0,48), slab1: [16,64)

    // ---- stage 48-row fp32 slab for this channel group ----
    {
        const float* gsrc = inp + (size_t)(b * 32 + cg * CG) * HWP;
        for (int f = tid; f < SLAB_ROWS * CG * 17; f += 1024) {
            int vq = f % 17;                // float4 index within row (16 = pad)
            int r  = f / 17;                // r = u*16 + c
            int u  = r >> 4;
            int c  = r & 15;
            float4 val = make_float4(0.f, 0.f, 0.f, 0.f);
            if (vq < 16)
                val = *(const float4*)(gsrc + c * HWP + (ubase + u) * WW + 4 * vq);
            *(float4*)(s_in + r * ROWF + 4 * vq) = val;
        }
    }
    __syncthreads();

    float* s_wy = s_w + w * 72;
    float* s_wx = s_wy + 32;                // 40 entries, aligned window

    const int pbeg = (HWP * tile) / PTILES;
    const int pend = (HWP * (tile + 1)) / PTILES;

    for (int p = pbeg + w; p < pend; p += NWARPS) {
        const int idx = b * HWP + p;
        float ey = exPy[idx], sy = sigy[idx];
        float ex = exPx[idx], sx = sigx[idx];

        int u0 = max(0,      (int)ceilf (ey - KTRUNC * sy));
        int u1 = min(HH - 1, (int)floorf(ey + KTRUNC * sy));
        // balanced slab assignment; slab0 handles u1<=47, slab1 handles u0>=16
        int myslab = (u1 <= 47 && (u0 < 16 || ey < 31.5f)) ? 0 : 1;
        if (myslab != slab) continue;

        int v0 = max(0,      (int)ceilf (ex - KTRUNC * sx));
        int v1 = min(WW - 1, (int)floorf(ex + KTRUNC * sx));
        int v0a = v0 & ~3;                  // 16B-aligned window start

        // per-lane weights
        float invsy = 1.0f / sy, invsx = 1.0f / sx;
        int uu = u0 + lane;
        float dy = ((float)uu - ey) * invsy;
        float wy = (uu <= u1) ? __expf(-0.5f * dy * dy) : 0.0f;
        int vv = v0 + lane;
        float dx = ((float)vv - ex) * invsx;
        float wx = (vv <= v1) ? __expf(-0.5f * dx * dx) : 0.0f;

        float sumy = wy, sumx = wx;
        #pragma unroll
        for (int o = 16; o; o >>= 1) {
            sumy += __shfl_xor_sync(0xFFFFFFFFu, sumy, o);
            sumx += __shfl_xor_sync(0xFFFFFFFFu, sumx, o);
        }
        float invZ = 1.0f / (sumy * sumx + 1e-8f);

        s_wy[lane] = wy;
        s_wx[lane] = 0.0f;
        if (lane < 8) s_wx[32 + lane] = 0.0f;
        __syncwarp();
        if (lane <= v1 - v0) s_wx[(v0 - v0a) + lane] = wx;
        __syncwarp();

        // hoist this lane's wx chunks (chunk k = hf + 2j) into registers
        ull wxp[10];
        #pragma unroll
        for (int j = 0; j < 5; j++) {
            float4 c4 = *(const float4*)(s_wx + 4 * hf + 8 * j);
            PACK2(wxp[2 * j],     c4.x, c4.y);
            PACK2(wxp[2 * j + 1], c4.z, c4.w);
        }

        const int wu  = u1 - u0 + 1;                       // <= 31
        const int nch = ((v1 - v0a) >> 2) + 1;             // float4 chunks, <= 9
        const int mch = (nch + 1) >> 1;                    // chunks per half, <= 5

        const float* prow = s_in + ((u0 - ubase) * CG + cl) * ROWF + v0a + 4 * hf;
        ull acc2 = 0ULL;

#define INNER(MCH)                                                      \
        for (int t = 0; t < wu; t++) {                                  \
            float wyt = s_wy[t];                                        \
            ull wy2; PACK2(wy2, wyt, wyt);                              \
            ull s2 = 0ULL;                                              \
            _Pragma("unroll")                                           \
            for (int j = 0; j < MCH; j++) {                             \
                longlong2 d = *(const longlong2*)(prow + 8 * j);        \
                FMA2(s2, wxp[2 * j],     (ull)d.x, s2);                 \
                FMA2(s2, wxp[2 * j + 1], (ull)d.y, s2);                 \
            }                                                           \
            FMA2(acc2, wy2, s2, acc2);                                  \
            prow += CG * ROWF;                                          \
        }

        switch (mch) {
            case 1: INNER(1); break;
            case 2: INNER(2); break;
            case 3: INNER(3); break;
            case 4: INNER(4); break;
            default: INNER(5); break;
        }
#undef INNER

        float lo, hi;
        UNPACK2(lo, hi, acc2);
        float accc = lo + hi;
        float tot = accc + __shfl_xor_sync(0xFFFFFFFFu, accc, 16);
        if (hf == 0)
            out[(size_t)(b * 32 + cg * CG + cl) * HWP + p] = tot * invZ;
        __syncwarp();
    }
}

extern "C" void kernel_launch(void* const* d_in, const int* in_sizes, int n_in,
                              void* d_out, int out_size) {
    (void)in_sizes; (void)n_in; (void)out_size;
    const float* inp  = (const float*)d_in[0];
    const float* exPx = (const float*)d_in[1];
    const float* exPy = (const float*)d_in[2];
    const float* sigx = (const float*)d_in[3];
    const float* sigy = (const float*)d_in[4];
    float* out = (float*)d_out;

    cudaFuncSetAttribute(swapv2_kernel,
                         cudaFuncAttributeMaxDynamicSharedMemorySize, SMEM_BYTES);
    dim3 grid(PTILES, 4, 8);        // (tile, slab*2+cgroup, batch) = 288 blocks
    swapv2_kernel<<<grid, 1024, SMEM_BYTES>>>(inp, exPx, exPy, sigx, sigy, out);
}

// round 4
// speedup vs baseline: 2.0506x; 1.1975x over previous
#include <cuda_runtime.h>
#include <cuda_fp16.h>
#include <math.h>

// SwapV2: Gaussian soft-gather, 4.5-sigma truncated. B=8, C=32, H=W=64 fp32.
//
// R4: fp16 image in smem (2 B/MAC on the crossbar), fp32 math via cvt+FFMA2.
// lane = channel (32 ch/block). Two overlapping 48-row u-slabs per batch.
// Row stride 72 halves (144 B): lane stride mod 128 B = 16c -> the 8-lane
// LDS.128 phases hit disjoint 16B regions, conflict-free.

#define HH 64
#define WW 64
#define HWP 4096
#define CCN 32
#define SLAB_ROWS 48
#define ROWH 72
#define NWARPS 32
#define PTILES 9
#define KTRUNC 4.5f

#define SIN_HALVES (SLAB_ROWS * CCN * ROWH)        // 110592
#define SIN_BYTES  (SIN_HALVES * 2)                // 221184
#define SW_FLOATS  (NWARPS * 72)                   // wy[32] + wx[40] per warp
#define SMEM_BYTES (SIN_BYTES + SW_FLOATS * 4)     // 230400 <= 232448

typedef unsigned long long ull;

#define FMA2(d, a, b, c) asm("fma.rn.f32x2 %0, %1, %2, %3;" : "=l"(d) : "l"(a), "l"(b), "l"(c))
#define PACK2(d, lo, hi) asm("mov.b64 %0, {%1, %2};" : "=l"(d) : "f"(lo), "f"(hi))
#define UNPACK2(lo, hi, s) asm("mov.b64 {%0, %1}, %2;" : "=f"(lo), "=f"(hi) : "l"(s))

__global__ __launch_bounds__(1024, 1)
void swapv2_kernel(const float* __restrict__ inp,
                   const float* __restrict__ exPx,
                   const float* __restrict__ exPy,
                   const float* __restrict__ sigx,
                   const float* __restrict__ sigy,
                   float* __restrict__ out)
{
    extern __shared__ char smem[];
    __half* s_in = (__half*)smem;                  // [u(48)][c(32)][ROWH]
    float*  s_w  = (float*)(smem + SIN_BYTES);

    const int tid  = threadIdx.x;
    const int w    = tid >> 5;
    const int lane = tid & 31;
    const int tile = blockIdx.x;                   // 0..8
    const int slab = blockIdx.y;                   // 0..1
    const int b    = blockIdx.z;                   // 0..7
    const int ubase = slab * 16;                   // slab0 [0,48), slab1 [16,64)

    // ---- stage 48-row fp16 slab (all 32 channels), pads zeroed ----
    {
        const float* gsrc = inp + (size_t)b * CCN * HWP;
        for (int j = tid; j < SLAB_ROWS * CCN * 9; j += 1024) {
            int q = j % 9;                         // 16B chunk in row (8 = pad)
            int r = j / 9;                         // r = u*32 + c
            uint4 st = make_uint4(0u, 0u, 0u, 0u);
            if (q < 8) {
                int u = r >> 5, c = r & 31;
                const float* g = gsrc + (size_t)c * HWP + (ubase + u) * WW + 8 * q;
                float4 a = *(const float4*)g;
                float4 bb = *(const float4*)(g + 4);
                __half2 h0 = __float22half2_rn(make_float2(a.x, a.y));
                __half2 h1 = __float22half2_rn(make_float2(a.z, a.w));
                __half2 h2 = __float22half2_rn(make_float2(bb.x, bb.y));
                __half2 h3 = __float22half2_rn(make_float2(bb.z, bb.w));
                st.x = *(unsigned*)&h0; st.y = *(unsigned*)&h1;
                st.z = *(unsigned*)&h2; st.w = *(unsigned*)&h3;
            }
            *(uint4*)(s_in + r * ROWH + 8 * q) = st;
        }
    }
    __syncthreads();

    float* s_wy = s_w + w * 72;
    float* s_wx = s_wy + 32;                       // 40 entries

    const int pbeg = (HWP * tile) / PTILES;
    const int pend = (HWP * (tile + 1)) / PTILES;

    for (int p = pbeg + w; p < pend; p += NWARPS) {
        const int idx = b * HWP + p;
        float ey = exPy[idx], sy = sigy[idx];

        int u0 = max(0,      (int)ceilf (ey - KTRUNC * sy));
        int u1 = min(HH - 1, (int)floorf(ey + KTRUNC * sy));
        int myslab = (u1 <= 47 && (u0 < 16 || ey < 31.5f)) ? 0 : 1;
        if (myslab != slab) continue;

        float ex = exPx[idx], sx = sigx[idx];
        int v0 = max(0,      (int)ceilf (ex - KTRUNC * sx));
        int v1 = min(WW - 1, (int)floorf(ex + KTRUNC * sx));
        int v0a = v0 & ~7;                          // 16B-aligned window start

        // per-lane weights (wx round-tripped through fp16 so Z matches products)
        float invsy = 1.0f / sy, invsx = 1.0f / sx;
        int uu = u0 + lane;
        float dy = ((float)uu - ey) * invsy;
        float wy = (uu <= u1) ? __expf(-0.5f * dy * dy) : 0.0f;
        int vv = v0 + lane;
        float dx = ((float)vv - ex) * invsx;
        float wx = (vv <= v1) ? __expf(-0.5f * dx * dx) : 0.0f;

        float sumy = wy, sumx = wx;
        #pragma unroll
        for (int o = 16; o; o >>= 1) {
            sumy += __shfl_xor_sync(0xFFFFFFFFu, sumy, o);
            sumx += __shfl_xor_sync(0xFFFFFFFFu, sumx, o);
        }
        float invZ = 1.0f / (sumy * sumx + 1e-8f);

        s_wy[lane] = wy;
        s_wx[lane] = 0.0f;
        if (lane < 8) s_wx[32 + lane] = 0.0f;
        __syncwarp();
        if (lane <= v1 - v0) s_wx[(v0 - v0a) + lane] = wx;
        __syncwarp();

        // hoist wx into registers as f32x2 pairs (<=5 chunks of 8)
        ull wxp[20];
        #pragma unroll
        for (int j = 0; j < 5; j++) {
            float4 a = *(const float4*)(s_wx + 8 * j);
            float4 bq = *(const float4*)(s_wx + 8 * j + 4);
            PACK2(wxp[4 * j + 0], a.x, a.y);
            PACK2(wxp[4 * j + 1], a.z, a.w);
            PACK2(wxp[4 * j + 2], bq.x, bq.y);
            PACK2(wxp[4 * j + 3], bq.z, bq.w);
        }

        const int wu  = u1 - u0 + 1;                // <= 28
        const int mch = ((v1 - v0a) >> 3) + 1;      // 8-half chunks, <= 5

        const __half* prow = s_in + ((u0 - ubase) * CCN + lane) * ROWH + v0a;
        ull acc2 = 0ULL;

#define INNER(MCH)                                                        \
        for (int t = 0; t < wu; t++) {                                    \
            float wyt = s_wy[t];                                          \
            ull wy2; PACK2(wy2, wyt, wyt);                                \
            ull s2 = 0ULL;                                                \
            _Pragma("unroll")                                             \
            for (int j = 0; j < MCH; j++) {                               \
                uint4 d = *(const uint4*)(prow + 8 * j);                  \
                float2 f0 = __half22float2(*(const __half2*)&d.x);        \
                float2 f1 = __half22float2(*(const __half2*)&d.y);        \
                float2 f2 = __half22float2(*(const __half2*)&d.z);        \
                float2 f3 = __half22float2(*(const __half2*)&d.w);        \
                ull p0, p1, p2, p3;                                       \
                PACK2(p0, f0.x, f0.y); PACK2(p1, f1.x, f1.y);             \
                PACK2(p2, f2.x, f2.y); PACK2(p3, f3.x, f3.y);             \
                FMA2(s2, wxp[4 * j + 0], p0, s2);                         \
                FMA2(s2, wxp[4 * j + 1], p1, s2);                         \
                FMA2(s2, wxp[4 * j + 2], p2, s2);                         \
                FMA2(s2, wxp[4 * j + 3], p3, s2);                         \
            }                                                             \
            FMA2(acc2, wy2, s2, acc2);                                    \
            prow += CCN * ROWH;                                           \
        }

        switch (mch) {
            case 1: INNER(1); break;
            case 2: INNER(2); break;
            case 3: INNER(3); break;
            case 4: INNER(4); break;
            default: INNER(5); break;
        }
#undef INNER

        float lo, hi;
        UNPACK2(lo, hi, acc2);
        out[(size_t)(b * CCN + lane) * HWP + p] = (lo + hi) * invZ;
        __syncwarp();
    }
}

extern "C" void kernel_launch(void* const* d_in, const int* in_sizes, int n_in,
                              void* d_out, int out_size) {
    (void)in_sizes; (void)n_in; (void)out_size;
    const float* inp  = (const float*)d_in[0];
    const float* exPx = (const float*)d_in[1];
    const float* exPy = (const float*)d_in[2];
    const float* sigx = (const float*)d_in[3];
    const float* sigy = (const float*)d_in[4];
    float* out = (float*)d_out;

    cudaFuncSetAttribute(swapv2_kernel,
                         cudaFuncAttributeMaxDynamicSharedMemorySize, SMEM_BYTES);
    dim3 grid(PTILES, 2, 8);        // 144 blocks = one full wave
    swapv2_kernel<<<grid, 1024, SMEM_BYTES>>>(inp, exPx, exPy, sigx, sigy, out);
}

// round 5
// speedup vs baseline: 2.2486x; 1.0965x over previous
#include <cuda_runtime.h>
#include <cuda_fp16.h>
#include <math.h>

// SwapV2: Gaussian soft-gather, 4.5-sigma truncated. B=8, C=32, H=W=64 fp32.
// R5: R4 + (a) smem pixel list + atomic work queue for warp balance,
//     (b) 2-row unrolled inner loop with 4 split accumulators for ILP,
//     (c) reg-aware wx hoisting (mch<=3 in regs, 4..5 via broadcast LDS).

#define HH 64
#define WW 64
#define HWP 4096
#define CCN 32
#define SLAB_ROWS 48
#define ROWH 72
#define CROW (CCN * ROWH)
#define NWARPS 32
#define PTILES 9
#define KTRUNC 4.5f
#define LIST_N 464

#define SIN_HALVES (SLAB_ROWS * CCN * ROWH)
#define SIN_BYTES  (SIN_HALVES * 2)                 // 221184
#define SW_BYTES   (NWARPS * 72 * 4)                // 9216
#define SMEM_BYTES (SIN_BYTES + SW_BYTES + LIST_N * 4 + 8)  // 232264

typedef unsigned long long ull;

#define FMA2(d, a, b, c) asm("fma.rn.f32x2 %0, %1, %2, %3;" : "=l"(d) : "l"(a), "l"(b), "l"(c))
#define PACK2(d, lo, hi) asm("mov.b64 %0, {%1, %2};" : "=l"(d) : "f"(lo), "f"(hi))
#define UNPACK2(lo, hi, s) asm("mov.b64 {%0, %1}, %2;" : "=f"(lo), "=f"(hi) : "l"(s))

#define CVTP(d0, d1, ua, ub) {                                  \
    float2 _f0 = __half22float2(*(const __half2*)&(ua));        \
    float2 _f1 = __half22float2(*(const __half2*)&(ub));        \
    PACK2(d0, _f0.x, _f0.y); PACK2(d1, _f1.x, _f1.y); }

// body shared by both variants; WX(j,i) yields the f32x2 wx pair
#define BODY(MCH, WXPREP, WX)                                               \
    for (int t = 0; t < wu; t += 2) {                                       \
        float2 wyf = *(const float2*)(s_wy + t);                            \
        ull wyA; PACK2(wyA, wyf.x, wyf.x);                                  \
        ull wyB; PACK2(wyB, wyf.y, wyf.y);                                  \
        const __half* pa = prow;                                            \
        const __half* pb = (t + 1 < wu) ? prow + CROW : prow;               \
        ull sA0 = 0, sA1 = 0, sB0 = 0, sB1 = 0;                             \
        _Pragma("unroll")                                                   \
        for (int j = 0; j < MCH; j++) {                                     \
            uint4 dA = *(const uint4*)(pa + 8 * j);                         \
            uint4 dB = *(const uint4*)(pb + 8 * j);                         \
            WXPREP                                                          \
            ull q0, q1, q2, q3;                                             \
            CVTP(q0, q1, dA.x, dA.y); CVTP(q2, q3, dA.z, dA.w);             \
            FMA2(sA0, WX(j,0), q0, sA0); FMA2(sA1, WX(j,1), q1, sA1);       \
            FMA2(sA0, WX(j,2), q2, sA0); FMA2(sA1, WX(j,3), q3, sA1);       \
            CVTP(q0, q1, dB.x, dB.y); CVTP(q2, q3, dB.z, dB.w);             \
            FMA2(sB0, WX(j,0), q0, sB0); FMA2(sB1, WX(j,1), q1, sB1);       \
            FMA2(sB0, WX(j,2), q2, sB0); FMA2(sB1, WX(j,3), q3, sB1);       \
        }                                                                   \
        FMA2(acc0, wyA, sA0, acc0); FMA2(acc1, wyA, sA1, acc1);             \
        FMA2(acc0, wyB, sB0, acc0); FMA2(acc1, wyB, sB1, acc1);             \
        prow += 2 * CROW;                                                   \
    }

#define WXR(j,i) wxp[4*(j)+(i)]
#define INNER_R(MCH) {                                                      \
    ull wxp[4 * MCH];                                                       \
    _Pragma("unroll")                                                       \
    for (int j = 0; j < MCH; j++) {                                         \
        float4 a = *(const float4*)(s_wx + 8 * j);                          \
        float4 bq = *(const float4*)(s_wx + 8 * j + 4);                     \
        PACK2(wxp[4*j+0], a.x, a.y); PACK2(wxp[4*j+1], a.z, a.w);           \
        PACK2(wxp[4*j+2], bq.x, bq.y); PACK2(wxp[4*j+3], bq.z, bq.w);       \
    }                                                                       \
    BODY(MCH, , WXR) }

#define WXS(j,i) wxs[i]
#define INNER_S(MCH) {                                                      \
    BODY(MCH,                                                               \
        ull wxs[4];                                                         \
        { float4 a = *(const float4*)(s_wx + 8 * j);                        \
          float4 bq = *(const float4*)(s_wx + 8 * j + 4);                   \
          PACK2(wxs[0], a.x, a.y); PACK2(wxs[1], a.z, a.w);                 \
          PACK2(wxs[2], bq.x, bq.y); PACK2(wxs[3], bq.z, bq.w); },          \
        WXS) }

__global__ __launch_bounds__(1024, 1)
void swapv2_kernel(const float* __restrict__ inp,
                   const float* __restrict__ exPx,
                   const float* __restrict__ exPy,
                   const float* __restrict__ sigx,
                   const float* __restrict__ sigy,
                   float* __restrict__ out)
{
    extern __shared__ char smem[];
    __half* s_in  = (__half*)smem;                         // [48][32][ROWH]
    float*  s_w   = (float*)(smem + SIN_BYTES);
    int*    s_list = (int*)(smem + SIN_BYTES + SW_BYTES);
    int*    s_cnt  = s_list + LIST_N;                      // [0]=count,[1]=next

    const int tid  = threadIdx.x;
    const int w    = tid >> 5;
    const int lane = tid & 31;
    const int tile = blockIdx.x;                           // 0..8
    const int slab = blockIdx.y;                           // 0..1
    const int b    = blockIdx.z;                           // 0..7
    const int ubase = slab * 16;

    if (tid < 2) s_cnt[tid] = 0;
    __syncthreads();

    const int pbeg = (HWP * tile) / PTILES;
    const int pend = (HWP * (tile + 1)) / PTILES;

    // ---- build this block's pixel list (slab membership) ----
    for (int p = pbeg + tid; p < pend; p += 1024) {
        int idx = b * HWP + p;
        float ey = exPy[idx], sy = sigy[idx];
        int u0 = max(0,      (int)ceilf (ey - KTRUNC * sy));
        int u1 = min(HH - 1, (int)floorf(ey + KTRUNC * sy));
        int ms = (u1 <= 47 && (u0 < 16 || ey < 31.5f)) ? 0 : 1;
        if (ms == slab) s_list[atomicAdd(&s_cnt[0], 1)] = p;
    }

    // ---- stage 48-row fp16 slab (all 32 channels), pads zeroed ----
    {
        const float* gsrc = inp + (size_t)b * CCN * HWP;
        for (int j = tid; j < SLAB_ROWS * CCN * 9; j += 1024) {
            int q = j % 9;
            int r = j / 9;
            uint4 st = make_uint4(0u, 0u, 0u, 0u);
            if (q < 8) {
                int u = r >> 5, c = r & 31;
                const float* g = gsrc + (size_t)c * HWP + (ubase + u) * WW + 8 * q;
                float4 a = *(const float4*)g;
                float4 bb = *(const float4*)(g + 4);
                __half2 h0 = __float22half2_rn(make_float2(a.x, a.y));
                __half2 h1 = __float22half2_rn(make_float2(a.z, a.w));
                __half2 h2 = __float22half2_rn(make_float2(bb.x, bb.y));
                __half2 h3 = __float22half2_rn(make_float2(bb.z, bb.w));
                st.x = *(unsigned*)&h0; st.y = *(unsigned*)&h1;
                st.z = *(unsigned*)&h2; st.w = *(unsigned*)&h3;
            }
            *(uint4*)(s_in + r * ROWH + 8 * q) = st;
        }
    }
    __syncthreads();

    const int cnt = s_cnt[0];
    float* s_wy = s_w + w * 72;
    float* s_wx = s_wy + 32;

    // ---- dynamic work queue: warps pop pixels ----
    for (;;) {
        int k = 0;
        if (lane == 0) k = atomicAdd(&s_cnt[1], 1);
        k = __shfl_sync(0xFFFFFFFFu, k, 0);
        if (k >= cnt) break;
        const int p = s_list[k];
        const int idx = b * HWP + p;

        float ey = exPy[idx], sy = sigy[idx];
        float ex = exPx[idx], sx = sigx[idx];

        int u0 = max(0,      (int)ceilf (ey - KTRUNC * sy));
        int u1 = min(HH - 1, (int)floorf(ey + KTRUNC * sy));
        int v0 = max(0,      (int)ceilf (ex - KTRUNC * sx));
        int v1 = min(WW - 1, (int)floorf(ex + KTRUNC * sx));
        int v0a = v0 & ~7;

        float invsy = 1.0f / sy, invsx = 1.0f / sx;
        int uu = u0 + lane;
        float dy = ((float)uu - ey) * invsy;
        float wy = (uu <= u1) ? __expf(-0.5f * dy * dy) : 0.0f;
        int vv = v0 + lane;
        float dx = ((float)vv - ex) * invsx;
        float wx = (vv <= v1) ? __expf(-0.5f * dx * dx) : 0.0f;

        float sumy = wy, sumx = wx;
        #pragma unroll
        for (int o = 16; o; o >>= 1) {
            sumy += __shfl_xor_sync(0xFFFFFFFFu, sumy, o);
            sumx += __shfl_xor_sync(0xFFFFFFFFu, sumx, o);
        }
        float invZ = 1.0f / (sumy * sumx + 1e-8f);

        s_wy[lane] = wy;
        s_wx[lane] = 0.0f;
        if (lane < 8) s_wx[32 + lane] = 0.0f;
        __syncwarp();
        if (lane <= v1 - v0) s_wx[(v0 - v0a) + lane] = wx;
        __syncwarp();

        const int wu  = u1 - u0 + 1;                 // <= 28
        const int mch = ((v1 - v0a) >> 3) + 1;       // <= 5

        const __half* prow = s_in + ((u0 - ubase) * CCN + lane) * ROWH + v0a;
        ull acc0 = 0ULL, acc1 = 0ULL;

        switch (mch) {
            case 1: INNER_R(1); break;
            case 2: INNER_R(2); break;
            case 3: INNER_R(3); break;
            case 4: INNER_S(4); break;
            default: INNER_S(5); break;
        }

        float l0, h0q, l1, h1q;
        UNPACK2(l0, h0q, acc0);
        UNPACK2(l1, h1q, acc1);
        out[(size_t)(b * CCN + lane) * HWP + p] = (l0 + h0q + l1 + h1q) * invZ;
        __syncwarp();
    }
}

extern "C" void kernel_launch(void* const* d_in, const int* in_sizes, int n_in,
                              void* d_out, int out_size) {
    (void)in_sizes; (void)n_in; (void)out_size;
    const float* inp  = (const float*)d_in[0];
    const float* exPx = (const float*)d_in[1];
    const float* exPy = (const float*)d_in[2];
    const float* sigx = (const float*)d_in[3];
    const float* sigy = (const float*)d_in[4];
    float* out = (float*)d_out;

    cudaFuncSetAttribute(swapv2_kernel,
                         cudaFuncAttributeMaxDynamicSharedMemorySize, SMEM_BYTES);
    dim3 grid(PTILES, 2, 8);          // 144 blocks = one full wave
    swapv2_kernel<<<grid, 1024, SMEM_BYTES>>>(inp, exPx, exPy, sigx, sigy, out);
}

// round 6
// speedup vs baseline: 3.0767x; 1.3682x over previous
#include <cuda_runtime.h>
#include <cuda_fp16.h>
#include <math.h>

// SwapV2: Gaussian soft-gather, 4-sigma truncated. B=8, C=32, H=W=64 fp32.
// R6: fp16 chunk-local accumulation (4-deep HFMA2 per 16B chunk), chunk sums
// converted to fp32 and weighted by wy via FFMA2. Work queue + 2-row unroll
// retained from R5. wx stored as fp16 (Z computed from rounded wx).

#define HH 64
#define WW 64
#define HWP 4096
#define CCN 32
#define SLAB_ROWS 48
#define ROWH 72
#define CROW (CCN * ROWH)
#define NWARPS 32
#define PTILES 9
#define KTRUNC 4.0f
#define LIST_N 464

#define SIN_HALVES (SLAB_ROWS * CCN * ROWH)
#define SIN_BYTES  (SIN_HALVES * 2)                 // 221184
#define SW_BYTES   (NWARPS * 256)                   // wy[32]f32 + wx[48]h per warp
#define SMEM_BYTES (SIN_BYTES + SW_BYTES + LIST_N * 4 + 8)

typedef unsigned long long ull;

#define FMA2(d, a, b, c) asm("fma.rn.f32x2 %0, %1, %2, %3;" : "=l"(d) : "l"(a), "l"(b), "l"(c))
#define PACK2(d, lo, hi) asm("mov.b64 %0, {%1, %2};" : "=l"(d) : "f"(lo), "f"(hi))
#define UNPACK2(lo, hi, s) asm("mov.b64 {%0, %1}, %2;" : "=f"(lo), "=f"(hi) : "l"(s))

#define H2(x) (*(const __half2*)&(x))

// per-chunk: fp16 4-chain -> f32 pair -> FFMA2 with wy
#define CHUNK(dst, wq, d, wy2) {                                    \
    __half2 _h = __hmul2(H2((wq).x), H2((d).x));                    \
    _h = __hfma2(H2((wq).y), H2((d).y), _h);                        \
    _h = __hfma2(H2((wq).z), H2((d).z), _h);                        \
    _h = __hfma2(H2((wq).w), H2((d).w), _h);                        \
    float2 _f = __half22float2(_h);                                 \
    ull _q; PACK2(_q, _f.x, _f.y);                                  \
    FMA2(dst, wy2, _q, dst); }

#define BODY(MCH) {                                                 \
    uint4 wxq[MCH];                                                 \
    _Pragma("unroll")                                               \
    for (int j = 0; j < MCH; j++)                                   \
        wxq[j] = *(const uint4*)(s_wxh + 8 * j);                    \
    for (int t = 0; t < wu; t += 2) {                               \
        float2 wyf = *(const float2*)(s_wy + t);                    \
        ull wyA; PACK2(wyA, wyf.x, wyf.x);                          \
        ull wyB; PACK2(wyB, wyf.y, wyf.y);                          \
        const __half* pa = prow;                                    \
        const __half* pb = (t + 1 < wu) ? prow + CROW : prow;       \
        _Pragma("unroll")                                           \
        for (int j = 0; j < MCH; j++) {                             \
            uint4 dA = *(const uint4*)(pa + 8 * j);                 \
            uint4 dB = *(const uint4*)(pb + 8 * j);                 \
            CHUNK(accA, wxq[j], dA, wyA);                           \
            CHUNK(accB, wxq[j], dB, wyB);                           \
        }                                                           \
        prow += 2 * CROW;                                           \
    } }

__global__ __launch_bounds__(1024, 1)
void swapv2_kernel(const float* __restrict__ inp,
                   const float* __restrict__ exPx,
                   const float* __restrict__ exPy,
                   const float* __restrict__ sigx,
                   const float* __restrict__ sigy,
                   float* __restrict__ out)
{
    extern __shared__ char smem[];
    __half* s_in  = (__half*)smem;                          // [48][32][ROWH]
    char*   s_wb  = smem + SIN_BYTES;                       // per-warp 256B
    int*    s_list = (int*)(smem + SIN_BYTES + SW_BYTES);
    int*    s_cnt  = s_list + LIST_N;

    const int tid  = threadIdx.x;
    const int w    = tid >> 5;
    const int lane = tid & 31;
    const int tile = blockIdx.x;                            // 0..8
    const int slab = blockIdx.y;                            // 0..1
    const int b    = blockIdx.z;                            // 0..7
    const int ubase = slab * 16;

    if (tid < 2) s_cnt[tid] = 0;
    __syncthreads();

    const int pbeg = (HWP * tile) / PTILES;
    const int pend = (HWP * (tile + 1)) / PTILES;

    // ---- build pixel list (slab membership) ----
    for (int p = pbeg + tid; p < pend; p += 1024) {
        int idx = b * HWP + p;
        float ey = exPy[idx], sy = sigy[idx];
        int u0 = max(0,      (int)ceilf (ey - KTRUNC * sy));
        int u1 = min(HH - 1, (int)floorf(ey + KTRUNC * sy));
        int ms = (u1 <= 47 && (u0 < 16 || ey < 31.5f)) ? 0 : 1;
        if (ms == slab) s_list[atomicAdd(&s_cnt[0], 1)] = p;
    }

    // ---- stage 48-row fp16 slab, pads zeroed ----
    {
        const float* gsrc = inp + (size_t)b * CCN * HWP;
        for (int j = tid; j < SLAB_ROWS * CCN * 9; j += 1024) {
            int q = j % 9;
            int r = j / 9;
            uint4 st = make_uint4(0u, 0u, 0u, 0u);
            if (q < 8) {
                int u = r >> 5, c = r & 31;
                const float* g = gsrc + (size_t)c * HWP + (ubase + u) * WW + 8 * q;
                float4 a = *(const float4*)g;
                float4 bb = *(const float4*)(g + 4);
                __half2 h0 = __float22half2_rn(make_float2(a.x, a.y));
                __half2 h1 = __float22half2_rn(make_float2(a.z, a.w));
                __half2 h2 = __float22half2_rn(make_float2(bb.x, bb.y));
                __half2 h3 = __float22half2_rn(make_float2(bb.z, bb.w));
                st.x = *(unsigned*)&h0; st.y = *(unsigned*)&h1;
                st.z = *(unsigned*)&h2; st.w = *(unsigned*)&h3;
            }
            *(uint4*)(s_in + r * ROWH + 8 * q) = st;
        }
    }
    __syncthreads();

    const int cnt = s_cnt[0];
    float*  s_wy  = (float*)(s_wb + w * 256);               // 32 f32
    __half* s_wxh = (__half*)(s_wb + w * 256 + 128);        // 48 halves

    // ---- dynamic work queue ----
    for (;;) {
        int k = 0;
        if (lane == 0) k = atomicAdd(&s_cnt[1], 1);
        k = __shfl_sync(0xFFFFFFFFu, k, 0);
        if (k >= cnt) break;
        const int p = s_list[k];
        const int idx = b * HWP + p;

        float ey = exPy[idx], sy = sigy[idx];
        float ex = exPx[idx], sx = sigx[idx];

        int u0 = max(0,      (int)ceilf (ey - KTRUNC * sy));
        int u1 = min(HH - 1, (int)floorf(ey + KTRUNC * sy));
        int v0 = max(0,      (int)ceilf (ex - KTRUNC * sx));
        int v1 = min(WW - 1, (int)floorf(ex + KTRUNC * sx));
        int v0a = v0 & ~7;

        float invsy = 1.0f / sy, invsx = 1.0f / sx;
        int uu = u0 + lane;
        float dy = ((float)uu - ey) * invsy;
        float wy = (uu <= u1) ? __expf(-0.5f * dy * dy) : 0.0f;
        int vv = v0 + lane;
        float dx = ((float)vv - ex) * invsx;
        float wxf = (vv <= v1) ? __expf(-0.5f * dx * dx) : 0.0f;
        __half wxh = __float2half_rn(wxf);
        float wxr = __half2float(wxh);       // Z must match fp16 weights

        float sumy = wy, sumx = wxr;
        #pragma unroll
        for (int o = 16; o; o >>= 1) {
            sumy += __shfl_xor_sync(0xFFFFFFFFu, sumy, o);
            sumx += __shfl_xor_sync(0xFFFFFFFFu, sumx, o);
        }
        float invZ = 1.0f / (sumy * sumx + 1e-8f);

        s_wy[lane] = wy;
        if (lane < 24) ((unsigned*)s_wxh)[lane] = 0u;
        __syncwarp();
        if (lane <= v1 - v0) s_wxh[(v0 - v0a) + lane] = wxh;
        __syncwarp();

        const int wu  = u1 - u0 + 1;                 // <= 25
        const int mch = ((v1 - v0a) >> 3) + 1;       // <= 5

        const __half* prow = s_in + ((u0 - ubase) * CCN + lane) * ROWH + v0a;
        ull accA = 0ULL, accB = 0ULL;

        switch (mch) {
            case 1: BODY(1); break;
            case 2: BODY(2); break;
            case 3: BODY(3); break;
            case 4: BODY(4); break;
            default: BODY(5); break;
        }

        float a0, a1, b0, b1;
        UNPACK2(a0, a1, accA);
        UNPACK2(b0, b1, accB);
        out[(size_t)(b * CCN + lane) * HWP + p] = (a0 + a1 + b0 + b1) * invZ;
        __syncwarp();
    }
}

extern "C" void kernel_launch(void* const* d_in, const int* in_sizes, int n_in,
                              void* d_out, int out_size) {
    (void)in_sizes; (void)n_in; (void)out_size;
    const float* inp  = (const float*)d_in[0];
    const float* exPx = (const float*)d_in[1];
    const float* exPy = (const float*)d_in[2];
    const float* sigx = (const float*)d_in[3];
    const float* sigy = (const float*)d_in[4];
    float* out = (float*)d_out;

    cudaFuncSetAttribute(swapv2_kernel,
                         cudaFuncAttributeMaxDynamicSharedMemorySize, SMEM_BYTES);
    dim3 grid(PTILES, 2, 8);          // 144 blocks = one full wave
    swapv2_kernel<<<grid, 1024, SMEM_BYTES>>>(inp, exPx, exPy, sigx, sigy, out);
}

// round 8
// speedup vs baseline: 3.1588x; 1.0267x over previous
#include <cuda_runtime.h>
#include <cuda_fp16.h>
#include <math.h>

// SwapV2: Gaussian soft-gather, 3.75-sigma truncated. B=8, C=32, H=W=64 fp32.
// R8: R7 with the OOB speculative-row bug fixed: every speculative row
// pointer (pb/pc/pd) clamps to a valid row (wy=0 masks the duplicate).
// Reading ARBITRARY smem under a zero weight is NOT safe (NaN*0=NaN).

#define HH 64
#define WW 64
#define HWP 4096
#define CCN 32
#define SLAB_ROWS 48
#define ROWH 72
#define CROW (CCN * ROWH)
#define NWARPS 32
#define PTILES 9
#define KTRUNC 3.75f
#define LIST_N 464

#define SIN_HALVES (SLAB_ROWS * CCN * ROWH)
#define SIN_BYTES  (SIN_HALVES * 2)                 // 221184
#define SW_BYTES   (NWARPS * 256)                   // wy[32]f32 + wx[48]h per warp
#define SMEM_BYTES (SIN_BYTES + SW_BYTES + LIST_N * 4 + 8)

typedef unsigned long long ull;

#define FMA2(d, a, b, c) asm("fma.rn.f32x2 %0, %1, %2, %3;" : "=l"(d) : "l"(a), "l"(b), "l"(c))
#define PACK2(d, lo, hi) asm("mov.b64 %0, {%1, %2};" : "=l"(d) : "f"(lo), "f"(hi))
#define UNPACK2(lo, hi, s) asm("mov.b64 {%0, %1}, %2;" : "=f"(lo), "=f"(hi) : "l"(s))

#define H2(x) (*(const __half2*)&(x))

// per-chunk: fp16 4-chain -> f32 pair -> FFMA2 with wy
#define CHUNK(dst, wq, d, wy2) {                                    \
    __half2 _h = __hmul2(H2((wq).x), H2((d).x));                    \
    _h = __hfma2(H2((wq).y), H2((d).y), _h);                        \
    _h = __hfma2(H2((wq).z), H2((d).z), _h);                        \
    _h = __hfma2(H2((wq).w), H2((d).w), _h);                        \
    float2 _f = __half22float2(_h);                                 \
    ull _q; PACK2(_q, _f.x, _f.y);                                  \
    FMA2(dst, wy2, _q, dst); }

// 2-row unrolled body; speculative row t+1 CLAMPED to a valid row
#define BODY2(MCH) {                                                \
    uint4 wxq[MCH];                                                 \
    _Pragma("unroll")                                               \
    for (int j = 0; j < MCH; j++)                                   \
        wxq[j] = *(const uint4*)(s_wxh + 8 * j);                    \
    for (int t = 0; t < wu; t += 2) {                               \
        float2 wyf = *(const float2*)(s_wy + t);                    \
        ull wyA; PACK2(wyA, wyf.x, wyf.x);                          \
        ull wyB; PACK2(wyB, wyf.y, wyf.y);                          \
        const __half* pa = prow;                                    \
        const __half* pb = (t + 1 < wu) ? prow + CROW : prow;       \
        _Pragma("unroll")                                           \
        for (int j = 0; j < MCH; j++) {                             \
            uint4 dA = *(const uint4*)(pa + 8 * j);                 \
            uint4 dB = *(const uint4*)(pb + 8 * j);                 \
            CHUNK(accA, wxq[j], dA, wyA);                           \
            CHUNK(accB, wxq[j], dB, wyB);                           \
        }                                                           \
        prow += 2 * CROW;                                           \
    } }

// 4-row unrolled body for narrow windows; rows t+1..t+3 CLAMPED
#define BODY4(MCH) {                                                \
    uint4 wxq[MCH];                                                 \
    _Pragma("unroll")                                               \
    for (int j = 0; j < MCH; j++)                                   \
        wxq[j] = *(const uint4*)(s_wxh + 8 * j);                    \
    for (int t = 0; t < wu; t += 4) {                               \
        float4 wyf = *(const float4*)(s_wy + t);                    \
        ull wyA; PACK2(wyA, wyf.x, wyf.x);                          \
        ull wyB; PACK2(wyB, wyf.y, wyf.y);                          \
        ull wyC; PACK2(wyC, wyf.z, wyf.z);                          \
        ull wyD; PACK2(wyD, wyf.w, wyf.w);                          \
        const __half* pa = prow;                                    \
        const __half* pb = (t + 1 < wu) ? prow + CROW : prow;       \
        const __half* pc = (t + 2 < wu) ? prow + 2 * CROW : prow;   \
        const __half* pd = (t + 3 < wu) ? prow + 3 * CROW : prow;   \
        _Pragma("unroll")                                           \
        for (int j = 0; j < MCH; j++) {                             \
            uint4 dA = *(const uint4*)(pa + 8 * j);                 \
            uint4 dB = *(const uint4*)(pb + 8 * j);                 \
            uint4 dC = *(const uint4*)(pc + 8 * j);                 \
            uint4 dD = *(const uint4*)(pd + 8 * j);                 \
            CHUNK(accA, wxq[j], dA, wyA);                           \
            CHUNK(accB, wxq[j], dB, wyB);                           \
            CHUNK(accA, wxq[j], dC, wyC);                           \
            CHUNK(accB, wxq[j], dD, wyD);                           \
        }                                                           \
        prow += 4 * CROW;                                           \
    } }

__global__ __launch_bounds__(1024, 1)
void swapv2_kernel(const float* __restrict__ inp,
                   const float* __restrict__ exPx,
                   const float* __restrict__ exPy,
                   const float* __restrict__ sigx,
                   const float* __restrict__ sigy,
                   float* __restrict__ out)
{
    extern __shared__ char smem[];
    __half* s_in  = (__half*)smem;                          // [48][32][ROWH]
    char*   s_wb  = smem + SIN_BYTES;                       // per-warp 256B
    int*    s_list = (int*)(smem + SIN_BYTES + SW_BYTES);
    int*    s_cnt  = s_list + LIST_N;

    const int tid  = threadIdx.x;
    const int w    = tid >> 5;
    const int lane = tid & 31;
    const int tile = blockIdx.x;                            // 0..8
    const int slab = blockIdx.y;                            // 0..1
    const int b    = blockIdx.z;                            // 0..7
    const int ubase = slab * 16;

    if (tid < 2) s_cnt[tid] = 0;
    __syncthreads();

    const int pbeg = (HWP * tile) / PTILES;
    const int pend = (HWP * (tile + 1)) / PTILES;

    // ---- build pixel list (slab membership) ----
    for (int p = pbeg + tid; p < pend; p += 1024) {
        int idx = b * HWP + p;
        float ey = exPy[idx], sy = sigy[idx];
        int u0 = max(0,      (int)ceilf (ey - KTRUNC * sy));
        int u1 = min(HH - 1, (int)floorf(ey + KTRUNC * sy));
        int ms = (u1 <= 47 && (u0 < 16 || ey < 31.5f)) ? 0 : 1;
        if (ms == slab) s_list[atomicAdd(&s_cnt[0], 1)] = p;
    }

    // ---- stage 48-row fp16 slab, pads zeroed ----
    {
        const float* gsrc = inp + (size_t)b * CCN * HWP;
        for (int j = tid; j < SLAB_ROWS * CCN * 9; j += 1024) {
            int q = j % 9;
            int r = j / 9;
            uint4 st = make_uint4(0u, 0u, 0u, 0u);
            if (q < 8) {
                int u = r >> 5, c = r & 31;
                const float* g = gsrc + (size_t)c * HWP + (ubase + u) * WW + 8 * q;
                float4 a = *(const float4*)g;
                float4 bb = *(const float4*)(g + 4);
                __half2 h0 = __float22half2_rn(make_float2(a.x, a.y));
                __half2 h1 = __float22half2_rn(make_float2(a.z, a.w));
                __half2 h2 = __float22half2_rn(make_float2(bb.x, bb.y));
                __half2 h3 = __float22half2_rn(make_float2(bb.z, bb.w));
                st.x = *(unsigned*)&h0; st.y = *(unsigned*)&h1;
                st.z = *(unsigned*)&h2; st.w = *(unsigned*)&h3;
            }
            *(uint4*)(s_in + r * ROWH + 8 * q) = st;
        }
    }
    __syncthreads();

    const int cnt = s_cnt[0];
    float*  s_wy  = (float*)(s_wb + w * 256);               // 32 f32
    __half* s_wxh = (__half*)(s_wb + w * 256 + 128);        // 48 halves

    // ---- dynamic work queue ----
    for (;;) {
        int k = 0;
        if (lane == 0) k = atomicAdd(&s_cnt[1], 1);
        k = __shfl_sync(0xFFFFFFFFu, k, 0);
        if (k >= cnt) break;
        const int p = s_list[k];
        const int idx = b * HWP + p;

        float ey = exPy[idx], sy = sigy[idx];
        float ex = exPx[idx], sx = sigx[idx];

        int u0 = max(0,      (int)ceilf (ey - KTRUNC * sy));
        int u1 = min(HH - 1, (int)floorf(ey + KTRUNC * sy));
        int v0 = max(0,      (int)ceilf (ex - KTRUNC * sx));
        int v1 = min(WW - 1, (int)floorf(ex + KTRUNC * sx));
        int v0a = v0 & ~7;

        float invsy = 1.0f / sy, invsx = 1.0f / sx;
        int uu = u0 + lane;
        float dy = ((float)uu - ey) * invsy;
        float wy = (uu <= u1) ? __expf(-0.5f * dy * dy) : 0.0f;
        int vv = v0 + lane;
        float dx = ((float)vv - ex) * invsx;
        float wxf = (vv <= v1) ? __expf(-0.5f * dx * dx) : 0.0f;
        __half wxh = __float2half_rn(wxf);
        float wxr = __half2float(wxh);       // Z must match fp16 weights

        float sumy = wy, sumx = wxr;
        #pragma unroll
        for (int o = 16; o; o >>= 1) {
            sumy += __shfl_xor_sync(0xFFFFFFFFu, sumy, o);
            sumx += __shfl_xor_sync(0xFFFFFFFFu, sumx, o);
        }
        float invZ = 1.0f / (sumy * sumx + 1e-8f);

        s_wy[lane] = wy;
        if (lane < 24) ((unsigned*)s_wxh)[lane] = 0u;
        __syncwarp();
        if (lane <= v1 - v0) s_wxh[(v0 - v0a) + lane] = wxh;
        __syncwarp();

        const int wu  = u1 - u0 + 1;                 // <= 23
        const int mch = ((v1 - v0a) >> 3) + 1;       // <= 4

        const __half* prow = s_in + ((u0 - ubase) * CCN + lane) * ROWH + v0a;
        ull accA = 0ULL, accB = 0ULL;

        switch (mch) {
            case 1: BODY4(1); break;
            case 2: BODY4(2); break;
            case 3: BODY2(3); break;
            case 4: BODY2(4); break;
            default: BODY2(5); break;
        }

        float a0, a1, b0, b1;
        UNPACK2(a0, a1, accA);
        UNPACK2(b0, b1, accB);
        out[(size_t)(b * CCN + lane) * HWP + p] = (a0 + a1 + b0 + b1) * invZ;
        __syncwarp();
    }
}

extern "C" void kernel_launch(void* const* d_in, const int* in_sizes, int n_in,
                              void* d_out, int out_size) {
    (void)in_sizes; (void)n_in; (void)out_size;
    const float* inp  = (const float*)d_in[0];
    const float* exPx = (const float*)d_in[1];
    const float* exPy = (const float*)d_in[2];
    const float* sigx = (const float*)d_in[3];
    const float* sigy = (const float*)d_in[4];
    float* out = (float*)d_out;

    cudaFuncSetAttribute(swapv2_kernel,
                         cudaFuncAttributeMaxDynamicSharedMemorySize, SMEM_BYTES);
    dim3 grid(PTILES, 2, 8);          // 144 blocks = one full wave
    swapv2_kernel<<<grid, 1024, SMEM_BYTES>>>(inp, exPx, exPy, sigx, sigy, out);
}